// round 1
// baseline (speedup 1.0000x reference)
#include <cuda_runtime.h>
#include <cuda_bf16.h>
#include <cstdint>

// Problem constants
#define SEQ_LEN   2048
#define BATCH     16
#define HID       1024
#define N3        (3 * HID)            // 3072
#define MROWS     (SEQ_LEN * BATCH)    // 32768
#define SBH       (SEQ_LEN * BATCH * HID) // 33554432

// Scratch for U = input @ weight, layout [MROWS, N3] row-major (same as GEMM output)
__device__ float g_U[(size_t)MROWS * N3];

// ---------------------------------------------------------------------------
// SGEMM: C[M,N] = A[M,K] * B[K,N], M=32768, N=3072, K=1024, fp32
// Block tile 128x128, BK=8, 256 threads, 8x8 per thread.
// ---------------------------------------------------------------------------
#define BM 128
#define BN 128
#define BK 8

__global__ void __launch_bounds__(256, 2) sgemm128(
    const float* __restrict__ A, const float* __restrict__ B, float* __restrict__ C)
{
    __shared__ float As[BK][BM];
    __shared__ float Bs[BK][BN];

    const int tid = threadIdx.x;
    const int m0 = blockIdx.y * BM;
    const int n0 = blockIdx.x * BN;

    // A tile loads: 128 rows x 8 cols = 1024 floats = 256 float4
    const int arow = tid >> 1;           // 0..127
    const int acol = (tid & 1) << 2;     // 0 or 4
    // B tile loads: 8 rows x 128 cols
    const int brow = tid >> 5;           // 0..7
    const int bcol = (tid & 31) << 2;    // 0..124

    const int ty = tid >> 4;             // 0..15
    const int tx = tid & 15;             // 0..15

    const float* Aptr = A + (size_t)(m0 + arow) * 1024 + acol;
    const float* Bptr = B + (size_t)brow * N3 + n0 + bcol;

    float acc[8][8];
#pragma unroll
    for (int i = 0; i < 8; i++)
#pragma unroll
        for (int j = 0; j < 8; j++) acc[i][j] = 0.0f;

    for (int k0 = 0; k0 < 1024; k0 += BK) {
        float4 av = *(const float4*)(Aptr + k0);
        float4 bv = *(const float4*)(Bptr + (size_t)k0 * N3);

        As[acol + 0][arow] = av.x;
        As[acol + 1][arow] = av.y;
        As[acol + 2][arow] = av.z;
        As[acol + 3][arow] = av.w;
        *(float4*)&Bs[brow][bcol] = bv;
        __syncthreads();

#pragma unroll
        for (int k = 0; k < BK; k++) {
            float ra[8], rb[8];
            *(float4*)(ra)     = *(const float4*)&As[k][ty * 8];
            *(float4*)(ra + 4) = *(const float4*)&As[k][ty * 8 + 4];
            *(float4*)(rb)     = *(const float4*)&Bs[k][tx * 8];
            *(float4*)(rb + 4) = *(const float4*)&Bs[k][tx * 8 + 4];
#pragma unroll
            for (int i = 0; i < 8; i++)
#pragma unroll
                for (int j = 0; j < 8; j++)
                    acc[i][j] = fmaf(ra[i], rb[j], acc[i][j]);
        }
        __syncthreads();
    }

#pragma unroll
    for (int i = 0; i < 8; i++) {
        float* Crow = C + (size_t)(m0 + ty * 8 + i) * N3 + n0 + tx * 8;
        float4 v0 = make_float4(acc[i][0], acc[i][1], acc[i][2], acc[i][3]);
        float4 v1 = make_float4(acc[i][4], acc[i][5], acc[i][6], acc[i][7]);
        *(float4*)(Crow)     = v0;
        *(float4*)(Crow + 4) = v1;
    }
}

// ---------------------------------------------------------------------------
// SRU scan: one thread per (b, h) chain. 16384 threads, 2048 steps each.
// Group-of-8 prefetch: loads for group g+1 overlap compute of group g.
// Quirk preserved: v0,v1 are taken from bias (not v).
//   f = sigmoid(u0 + b0*c + b0); r = sigmoid(u1 + b1*c + b1)
//   c = f*c + (1-f)*u2 = u2 + f*(c - u2)
//   h = r*c + (1-r)*x  = x  + r*(c - x)
// ---------------------------------------------------------------------------
#define GS 8

__device__ __forceinline__ float sigmoid_fast(float x) {
    return __fdividef(1.0f, 1.0f + __expf(-x));
}

__global__ void __launch_bounds__(128) sru_scan(
    const float* __restrict__ U, const float* __restrict__ X,
    const float* __restrict__ bias,
    float* __restrict__ Hout, float* __restrict__ Cout)
{
    const int tid = blockIdx.x * blockDim.x + threadIdx.x; // 0..16383
    const int b = tid >> 10;
    const int h = tid & 1023;

    const float b0 = bias[h];
    const float b1 = bias[HID + h];

    const float* up = U + (size_t)b * N3 + 3 * h;
    const float* xp = X + (size_t)b * HID + h;
    float* hp = Hout + (size_t)b * HID + h;
    float* cp = Cout + (size_t)b * HID + h;

    const int USTEP = BATCH * N3;   // stride between timesteps in U
    const int XSTEP = BATCH * HID;  // stride between timesteps in X / outputs

    float c = 0.0f;

    float cu0[GS], cu1[GS], cu2[GS], cx[GS];
    // preload group 0; fold the +b into the load phase (off critical path)
#pragma unroll
    for (int i = 0; i < GS; i++) {
        const float* u = up + (size_t)i * USTEP;
        cu0[i] = u[0] + b0;
        cu1[i] = u[1] + b1;
        cu2[i] = u[2];
        cx[i]  = xp[(size_t)i * XSTEP];
    }

    const int NGROUPS = SEQ_LEN / GS;
    for (int tg = 0; tg < NGROUPS; tg++) {
        float nu0[GS], nu1[GS], nu2[GS], nx[GS];
        if (tg + 1 < NGROUPS) {
            const float* un = up + (size_t)(tg + 1) * GS * USTEP;
            const float* xn = xp + (size_t)(tg + 1) * GS * XSTEP;
#pragma unroll
            for (int i = 0; i < GS; i++) {
                const float* u = un + (size_t)i * USTEP;
                nu0[i] = u[0] + b0;
                nu1[i] = u[1] + b1;
                nu2[i] = u[2];
                nx[i]  = xn[(size_t)i * XSTEP];
            }
        }

#pragma unroll
        for (int i = 0; i < GS; i++) {
            const int t = tg * GS + i;
            float f = sigmoid_fast(fmaf(b0, c, cu0[i]));
            float r = sigmoid_fast(fmaf(b1, c, cu1[i]));
            float u2 = cu2[i];
            c = fmaf(f, c - u2, u2);
            float xv = cx[i];
            float hv = fmaf(r, c - xv, xv);
            hp[(size_t)t * XSTEP] = hv;
            cp[(size_t)t * XSTEP] = c;
        }

#pragma unroll
        for (int i = 0; i < GS; i++) {
            cu0[i] = nu0[i]; cu1[i] = nu1[i]; cu2[i] = nu2[i]; cx[i] = nx[i];
        }
    }
}

// ---------------------------------------------------------------------------
// Launch
// ---------------------------------------------------------------------------
extern "C" void kernel_launch(void* const* d_in, const int* in_sizes, int n_in,
                              void* d_out, int out_size)
{
    const float* input  = (const float*)d_in[0]; // [2048,16,1024]
    const float* weight = (const float*)d_in[1]; // [1024,3072]
    const float* bias   = (const float*)d_in[2]; // [2048]
    // d_in[3] = v, intentionally unused (source quirk)

    float* Hout = (float*)d_out;          // first SBH floats
    float* Cout = (float*)d_out + SBH;    // next SBH floats

    float* U;
    cudaGetSymbolAddress((void**)&U, g_U);

    dim3 ggrid(N3 / BN, MROWS / BM);      // (24, 256)
    sgemm128<<<ggrid, 256>>>(input, weight, U);

    sru_scan<<<BATCH * HID / 128, 128>>>(U, input, bias, Hout, Cout);
}

// round 3
// speedup vs baseline: 2.2832x; 2.2832x over previous
#include <cuda_runtime.h>
#include <cuda_bf16.h>
#include <cstdint>

// ---------------------------------------------------------------------------
// Problem constants
// ---------------------------------------------------------------------------
#define SEQ_LEN   2048
#define BATCH     16
#define HID       1024
#define N3        3072
#define KDIM      1024
#define MROWS     32768
#define SBH       (SEQ_LEN * BATCH * HID)  // 33554432

// Scratch (device globals; no runtime allocation allowed)
__device__ float         g_U [(size_t)MROWS * N3];    // GEMM output [M, 3H]
__device__ __nv_bfloat16 g_Ah[(size_t)MROWS * KDIM];  // input hi   [M,K]
__device__ __nv_bfloat16 g_Al[(size_t)MROWS * KDIM];  // input lo   [M,K]
__device__ __nv_bfloat16 g_Bh[(size_t)N3 * KDIM];     // weight^T hi [N,K]
__device__ __nv_bfloat16 g_Bl[(size_t)N3 * KDIM];     // weight^T lo [N,K]

// ---------------------------------------------------------------------------
// PTX helpers (base sm_103 only: cp.async + ldmatrix + mma.sync)
// ---------------------------------------------------------------------------
__device__ __forceinline__ uint32_t smem_u32(const void* p) {
    uint32_t a;
    asm("{ .reg .u64 t; cvta.to.shared.u64 t, %1; cvt.u32.u64 %0, t; }"
        : "=r"(a) : "l"(p));
    return a;
}

__device__ __forceinline__ void cpasync16(uint32_t dst, const void* src) {
    asm volatile("cp.async.cg.shared.global [%0], [%1], 16;"
        :: "r"(dst), "l"(src) : "memory");
}

__device__ __forceinline__ void ldsm_x4(uint32_t r[4], uint32_t addr) {
    asm volatile("ldmatrix.sync.aligned.m8n8.x4.shared.b16 {%0,%1,%2,%3}, [%4];"
        : "=r"(r[0]), "=r"(r[1]), "=r"(r[2]), "=r"(r[3]) : "r"(addr));
}

__device__ __forceinline__ void mma16816(float* c, const uint32_t* a,
                                         uint32_t b0, uint32_t b1) {
    asm volatile(
        "mma.sync.aligned.m16n8k16.row.col.f32.bf16.bf16.f32 "
        "{%0,%1,%2,%3}, {%4,%5,%6,%7}, {%8,%9}, {%0,%1,%2,%3};"
        : "+f"(c[0]), "+f"(c[1]), "+f"(c[2]), "+f"(c[3])
        : "r"(a[0]), "r"(a[1]), "r"(a[2]), "r"(a[3]), "r"(b0), "r"(b1));
}

// ---------------------------------------------------------------------------
// Conversion kernels: fp32 -> (bf16 hi, bf16 lo)
// ---------------------------------------------------------------------------
__device__ __forceinline__ void split_bf16(float x, __nv_bfloat16& h, __nv_bfloat16& l) {
    h = __float2bfloat16_rn(x);
    l = __float2bfloat16_rn(x - __bfloat162float(h));
}

__global__ void __launch_bounds__(256) convA(
    const float4* __restrict__ X, __nv_bfloat162* __restrict__ Ah2,
    __nv_bfloat162* __restrict__ Al2)
{
    size_t i = (size_t)blockIdx.x * blockDim.x + threadIdx.x;
    float4 v = X[i];
    __nv_bfloat16 h0, h1, h2, h3, l0, l1, l2, l3;
    split_bf16(v.x, h0, l0);
    split_bf16(v.y, h1, l1);
    split_bf16(v.z, h2, l2);
    split_bf16(v.w, h3, l3);
    Ah2[2 * i]     = __nv_bfloat162(h0, h1);
    Ah2[2 * i + 1] = __nv_bfloat162(h2, h3);
    Al2[2 * i]     = __nv_bfloat162(l0, l1);
    Al2[2 * i + 1] = __nv_bfloat162(l2, l3);
}

// Transpose weight [K,N3] -> [N3,K] and split
__global__ void __launch_bounds__(1024) convW(
    const float* __restrict__ W, __nv_bfloat16* __restrict__ Bh,
    __nv_bfloat16* __restrict__ Bl)
{
    __shared__ float t[32][33];
    int n0 = blockIdx.x * 32, k0 = blockIdx.y * 32;
    int tx = threadIdx.x, ty = threadIdx.y;
    t[ty][tx] = W[(size_t)(k0 + ty) * N3 + n0 + tx];
    __syncthreads();
    float v = t[tx][ty];   // = W[k0+tx][n0+ty]
    __nv_bfloat16 h, l;
    split_bf16(v, h, l);
    Bh[(size_t)(n0 + ty) * KDIM + k0 + tx] = h;
    Bl[(size_t)(n0 + ty) * KDIM + k0 + tx] = l;
}

// ---------------------------------------------------------------------------
// bf16x3 GEMM via mma.sync: U = Ah*Bh^T + Ah*Bl^T + Al*Bh^T (fp32 acc)
// CTA tile 128x128, warp tile 64x32 (2x4 warp grid), K-chunk 32.
// SMEM rows are 128B: [hi k0..31 (64B) | lo k0..31 (64B)], SW128-swizzled.
// 3-stage cp.async pipeline.
// ---------------------------------------------------------------------------
#define TK 32
#define NCHUNK (KDIM / TK)           // 32
#define TILE_BYTES 16384             // 128 rows x 128B
#define STAGE_BYTES (2 * TILE_BYTES) // A tile + B tile = 32KB
#define NSTAGE 3
#define GEMM_SMEM (1024 + NSTAGE * STAGE_BYTES)

__global__ void __launch_bounds__(256, 2) gemm_bf16x3(
    const __nv_bfloat16* __restrict__ Ah, const __nv_bfloat16* __restrict__ Al,
    const __nv_bfloat16* __restrict__ Bh, const __nv_bfloat16* __restrict__ Bl,
    float* __restrict__ U)
{
    extern __shared__ char dsm[];
    const uint32_t base = (smem_u32(dsm) + 1023) & ~1023u;

    const int tid = threadIdx.x;
    const int wid = tid >> 5, lid = tid & 31;
    const int m0 = blockIdx.y * 128;
    const int n0 = blockIdx.x * 128;
    const int wm = (wid >> 2) * 64;   // warp M offset (0 or 64)
    const int wn = (wid & 3) * 32;    // warp N offset (0,32,64,96)

    // --- loader geometry: thread t covers 8 16B-chunks (4 A rows, 4 B rows)
    // chunk q in [0,1024): row = q>>3, c = q&7 (c<4 -> hi, c>=4 -> lo)
    // phys = row*128 + ((c*16) ^ ((row&7)<<4))
    auto load_chunk = [&](int j, int s) {
        const uint32_t sb = base + s * STAGE_BYTES;
        const int koff = j * TK;
#pragma unroll
        for (int i = 0; i < 4; i++) {
            int q = i * 256 + tid;
            int r = q >> 3, c = q & 7;
            uint32_t sw = (uint32_t)(r * 128 + ((c * 16) ^ ((r & 7) << 4)));
            const __nv_bfloat16* src = (c < 4)
                ? (Ah + (size_t)(m0 + r) * KDIM + koff + c * 8)
                : (Al + (size_t)(m0 + r) * KDIM + koff + (c - 4) * 8);
            cpasync16(sb + sw, src);
        }
#pragma unroll
        for (int i = 0; i < 4; i++) {
            int q = i * 256 + tid;
            int r = q >> 3, c = q & 7;
            uint32_t sw = (uint32_t)(r * 128 + ((c * 16) ^ ((r & 7) << 4)));
            const __nv_bfloat16* src = (c < 4)
                ? (Bh + (size_t)(n0 + r) * KDIM + koff + c * 8)
                : (Bl + (size_t)(n0 + r) * KDIM + koff + (c - 4) * 8);
            cpasync16(sb + TILE_BYTES + sw, src);
        }
        asm volatile("cp.async.commit_group;" ::: "memory");
    };

    // --- per-lane ldmatrix address components
    const int fr = lid & 15;          // fragment row (m or n within 16)
    const int fc = lid >> 4;          // 16B chunk (k half: 0 or 1)
    const uint32_t axor = (uint32_t)((fr & 7) << 4);
    // byte-in-row for (part, ks): part*64 + ks*32 + fc*16, then ^ axor

    float acc[4][4][4];               // [mi][n8][frag]
#pragma unroll
    for (int a = 0; a < 4; a++)
#pragma unroll
        for (int b = 0; b < 4; b++)
#pragma unroll
            for (int q = 0; q < 4; q++) acc[a][b][q] = 0.0f;

    load_chunk(0, 0);
    load_chunk(1, 1);
    load_chunk(2, 2);

    for (int j = 0; j < NCHUNK; j++) {
        const int s = j % NSTAGE;
        asm volatile("cp.async.wait_group %0;" :: "n"(NSTAGE - 1) : "memory");
        __syncthreads();

        const uint32_t As = base + s * STAGE_BYTES;
        const uint32_t Bs = As + TILE_BYTES;

#pragma unroll
        for (int ks = 0; ks < 2; ks++) {
            // passes: (A part, B part) = (hi,hi), (hi,lo), (lo,hi)
#pragma unroll
            for (int p = 0; p < 3; p++) {
                const int ap = (p == 2) ? 1 : 0;
                const int bp = (p == 1) ? 1 : 0;
                const uint32_t abyte = (uint32_t)((ap * 64 + ks * 32 + fc * 16)) ^ axor;
                const uint32_t bbyte = (uint32_t)((bp * 64 + ks * 32 + fc * 16)) ^ axor;

                uint32_t afr[4][4];
#pragma unroll
                for (int mi = 0; mi < 4; mi++) {
                    uint32_t addr = As + (uint32_t)((wm + mi * 16 + fr) * 128) + abyte;
                    ldsm_x4(afr[mi], addr);
                }
                uint32_t bfr[2][4];
#pragma unroll
                for (int nj = 0; nj < 2; nj++) {
                    uint32_t addr = Bs + (uint32_t)((wn + nj * 16 + fr) * 128) + bbyte;
                    ldsm_x4(bfr[nj], addr);
                }
#pragma unroll
                for (int mi = 0; mi < 4; mi++) {
#pragma unroll
                    for (int n8 = 0; n8 < 4; n8++) {
                        // n8 tile: group nj = n8>>1, sub = n8&1
                        // regs: sub0 -> {r0, r2}, sub1 -> {r1, r3}
                        uint32_t b0 = bfr[n8 >> 1][(n8 & 1)];
                        uint32_t b1 = bfr[n8 >> 1][(n8 & 1) + 2];
                        mma16816(acc[mi][n8], afr[mi], b0, b1);
                    }
                }
            }
        }
        __syncthreads();
        if (j + NSTAGE < NCHUNK) load_chunk(j + NSTAGE, s);
    }

    // --- epilogue: acc -> U. C frag: lane l: c0,c1 at (row l/4, col 2(l%4)),
    // c2,c3 at row +8.
    const int crow = lid >> 2;
    const int ccol = (lid & 3) * 2;
#pragma unroll
    for (int mi = 0; mi < 4; mi++) {
#pragma unroll
        for (int n8 = 0; n8 < 4; n8++) {
            float* p0 = U + (size_t)(m0 + wm + mi * 16 + crow) * N3
                          + n0 + wn + n8 * 8 + ccol;
            float* p1 = p0 + (size_t)8 * N3;
            p0[0] = acc[mi][n8][0]; p0[1] = acc[mi][n8][1];
            p1[0] = acc[mi][n8][2]; p1[1] = acc[mi][n8][3];
        }
    }
}

// ---------------------------------------------------------------------------
// SRU scan (unchanged): one thread per (b,h), group-of-8 prefetch
// ---------------------------------------------------------------------------
#define GS 8

__device__ __forceinline__ float sigmoid_fast(float x) {
    return __fdividef(1.0f, 1.0f + __expf(-x));
}

__global__ void __launch_bounds__(128) sru_scan(
    const float* __restrict__ U, const float* __restrict__ X,
    const float* __restrict__ bias,
    float* __restrict__ Hout, float* __restrict__ Cout)
{
    const int tid = blockIdx.x * blockDim.x + threadIdx.x;
    const int b = tid >> 10;
    const int h = tid & 1023;

    const float b0 = bias[h];
    const float b1 = bias[HID + h];

    const float* up = U + (size_t)b * N3 + 3 * h;
    const float* xp = X + (size_t)b * HID + h;
    float* hp = Hout + (size_t)b * HID + h;
    float* cp = Cout + (size_t)b * HID + h;

    const int USTEP = BATCH * N3;
    const int XSTEP = BATCH * HID;

    float c = 0.0f;

    float cu0[GS], cu1[GS], cu2[GS], cx[GS];
#pragma unroll
    for (int i = 0; i < GS; i++) {
        const float* u = up + (size_t)i * USTEP;
        cu0[i] = u[0] + b0;
        cu1[i] = u[1] + b1;
        cu2[i] = u[2];
        cx[i]  = xp[(size_t)i * XSTEP];
    }

    const int NGROUPS = SEQ_LEN / GS;
    for (int tg = 0; tg < NGROUPS; tg++) {
        float nu0[GS], nu1[GS], nu2[GS], nx[GS];
        if (tg + 1 < NGROUPS) {
            const float* un = up + (size_t)(tg + 1) * GS * USTEP;
            const float* xn = xp + (size_t)(tg + 1) * GS * XSTEP;
#pragma unroll
            for (int i = 0; i < GS; i++) {
                const float* u = un + (size_t)i * USTEP;
                nu0[i] = u[0] + b0;
                nu1[i] = u[1] + b1;
                nu2[i] = u[2];
                nx[i]  = xn[(size_t)i * XSTEP];
            }
        }

#pragma unroll
        for (int i = 0; i < GS; i++) {
            const int t = tg * GS + i;
            float f = sigmoid_fast(fmaf(b0, c, cu0[i]));
            float r = sigmoid_fast(fmaf(b1, c, cu1[i]));
            float u2 = cu2[i];
            c = fmaf(f, c - u2, u2);
            float xv = cx[i];
            float hv = fmaf(r, c - xv, xv);
            hp[(size_t)t * XSTEP] = hv;
            cp[(size_t)t * XSTEP] = c;
        }

#pragma unroll
        for (int i = 0; i < GS; i++) {
            cu0[i] = nu0[i]; cu1[i] = nu1[i]; cu2[i] = nu2[i]; cx[i] = nx[i];
        }
    }
}

// ---------------------------------------------------------------------------
// Launch
// ---------------------------------------------------------------------------
extern "C" void kernel_launch(void* const* d_in, const int* in_sizes, int n_in,
                              void* d_out, int out_size)
{
    const float* input  = (const float*)d_in[0]; // [2048,16,1024]
    const float* weight = (const float*)d_in[1]; // [1024,3072]
    const float* bias   = (const float*)d_in[2]; // [2048]
    // d_in[3] = v, intentionally unused (source quirk)

    float* Hout = (float*)d_out;
    float* Cout = (float*)d_out + SBH;

    float *U; __nv_bfloat16 *Ah, *Al, *Bh, *Bl;
    cudaGetSymbolAddress((void**)&U,  g_U);
    cudaGetSymbolAddress((void**)&Ah, g_Ah);
    cudaGetSymbolAddress((void**)&Al, g_Al);
    cudaGetSymbolAddress((void**)&Bh, g_Bh);
    cudaGetSymbolAddress((void**)&Bl, g_Bl);

    cudaFuncSetAttribute(gemm_bf16x3,
                         cudaFuncAttributeMaxDynamicSharedMemorySize, GEMM_SMEM);

    convA<<<SBH / 4 / 256, 256>>>((const float4*)input,
                                  (__nv_bfloat162*)Ah, (__nv_bfloat162*)Al);
    convW<<<dim3(N3 / 32, KDIM / 32), dim3(32, 32)>>>(weight, Bh, Bl);

    gemm_bf16x3<<<dim3(N3 / 128, MROWS / 128), 256, GEMM_SMEM>>>(Ah, Al, Bh, Bl, U);

    sru_scan<<<BATCH * HID / 128, 128>>>(U, input, bias, Hout, Cout);
}

// round 4
// speedup vs baseline: 3.6544x; 1.6005x over previous
#include <cuda_runtime.h>
#include <cuda_fp16.h>
#include <cstdint>

// ---------------------------------------------------------------------------
// Problem constants
// ---------------------------------------------------------------------------
#define SEQ_LEN   2048
#define BATCH     16
#define HID       1024
#define N3        3072
#define KDIM      1024
#define MROWS     32768
#define SBH       (SEQ_LEN * BATCH * HID)  // 33554432

// Scratch (device globals; no runtime allocation allowed)
__device__ float  g_U [(size_t)MROWS * N3];    // GEMM output [M, 3H]
__device__ __half g_A [(size_t)MROWS * KDIM];  // input fp16  [M,K]
__device__ __half g_Bh[(size_t)N3 * KDIM];     // weight^T hi [N,K]
__device__ __half g_Bl[(size_t)N3 * KDIM];     // weight^T lo [N,K]

// ---------------------------------------------------------------------------
// PTX helpers (base sm_103: cp.async + ldmatrix + mma.sync)
// ---------------------------------------------------------------------------
__device__ __forceinline__ uint32_t smem_u32(const void* p) {
    uint32_t a;
    asm("{ .reg .u64 t; cvta.to.shared.u64 t, %1; cvt.u32.u64 %0, t; }"
        : "=r"(a) : "l"(p));
    return a;
}

__device__ __forceinline__ void cpasync16(uint32_t dst, const void* src) {
    asm volatile("cp.async.cg.shared.global [%0], [%1], 16;"
        :: "r"(dst), "l"(src) : "memory");
}

__device__ __forceinline__ void ldsm_x4(uint32_t r[4], uint32_t addr) {
    asm volatile("ldmatrix.sync.aligned.m8n8.x4.shared.b16 {%0,%1,%2,%3}, [%4];"
        : "=r"(r[0]), "=r"(r[1]), "=r"(r[2]), "=r"(r[3]) : "r"(addr));
}

__device__ __forceinline__ void mma16816(float* c, const uint32_t* a,
                                         uint32_t b0, uint32_t b1) {
    asm volatile(
        "mma.sync.aligned.m16n8k16.row.col.f32.f16.f16.f32 "
        "{%0,%1,%2,%3}, {%4,%5,%6,%7}, {%8,%9}, {%0,%1,%2,%3};"
        : "+f"(c[0]), "+f"(c[1]), "+f"(c[2]), "+f"(c[3])
        : "r"(a[0]), "r"(a[1]), "r"(a[2]), "r"(a[3]), "r"(b0), "r"(b1));
}

// ---------------------------------------------------------------------------
// Conversion kernels
// ---------------------------------------------------------------------------
__global__ void __launch_bounds__(256) convA(
    const float4* __restrict__ X, __half2* __restrict__ A2)
{
    size_t i = (size_t)blockIdx.x * blockDim.x + threadIdx.x;
    float4 v = X[i];
    A2[2 * i]     = __floats2half2_rn(v.x, v.y);
    A2[2 * i + 1] = __floats2half2_rn(v.z, v.w);
}

// Transpose weight [K,N3] -> [N3,K] and split into fp16 hi + lo
__global__ void __launch_bounds__(1024) convW(
    const float* __restrict__ W, __half* __restrict__ Bh,
    __half* __restrict__ Bl)
{
    __shared__ float t[32][33];
    int n0 = blockIdx.x * 32, k0 = blockIdx.y * 32;
    int tx = threadIdx.x, ty = threadIdx.y;
    t[ty][tx] = W[(size_t)(k0 + ty) * N3 + n0 + tx];
    __syncthreads();
    float v = t[tx][ty];   // = W[k0+tx][n0+ty]
    __half h = __float2half_rn(v);
    __half l = __float2half_rn(v - __half2float(h));
    Bh[(size_t)(n0 + ty) * KDIM + k0 + tx] = h;
    Bl[(size_t)(n0 + ty) * KDIM + k0 + tx] = l;
}

// ---------------------------------------------------------------------------
// fp16x2 GEMM via mma.sync: U = A*Bh^T + A*Bl^T (fp32 acc)
// CTA tile 128x128, warp tile 64x32 (2x4 warp grid), K-chunk 64.
// SMEM rows: 128B = 64 fp16 k-values, SW128 swizzle. 2-stage cp.async pipeline.
// A-fragments are reused across the Bh and Bl passes.
// ---------------------------------------------------------------------------
#define TKC 64
#define NCHUNK (KDIM / TKC)          // 16
#define TILE_BYTES 16384             // 128 rows x 128B
#define STAGE_BYTES (3 * TILE_BYTES) // A + Bh + Bl = 48KB
#define NSTAGE 2
#define GEMM_SMEM (1024 + NSTAGE * STAGE_BYTES)

__global__ void __launch_bounds__(256, 2) gemm_fp16x2(
    const __half* __restrict__ A, const __half* __restrict__ Bh,
    const __half* __restrict__ Bl, float* __restrict__ U)
{
    extern __shared__ char dsm[];
    const uint32_t base = (smem_u32(dsm) + 1023) & ~1023u;

    const int tid = threadIdx.x;
    const int wid = tid >> 5, lid = tid & 31;
    const int m0 = blockIdx.y * 128;
    const int n0 = blockIdx.x * 128;
    const int wm = (wid >> 2) * 64;   // warp M offset (0 or 64)
    const int wn = (wid & 3) * 32;    // warp N offset (0,32,64,96)

    // loader: 12 cp.async x 16B per thread per chunk (A, Bh, Bl tiles)
    auto load_chunk = [&](int j, int s) {
        const uint32_t sb = base + s * STAGE_BYTES;
        const int koff = j * TKC;
#pragma unroll
        for (int i = 0; i < 4; i++) {
            int q = i * 256 + tid;
            int r = q >> 3, c = q & 7;
            uint32_t sw = (uint32_t)(r * 128 + ((c * 16) ^ ((r & 7) << 4)));
            cpasync16(sb + sw,                  A  + (size_t)(m0 + r) * KDIM + koff + c * 8);
            cpasync16(sb + TILE_BYTES + sw,     Bh + (size_t)(n0 + r) * KDIM + koff + c * 8);
            cpasync16(sb + 2 * TILE_BYTES + sw, Bl + (size_t)(n0 + r) * KDIM + koff + c * 8);
        }
        asm volatile("cp.async.commit_group;" ::: "memory");
    };

    const int fr = lid & 15;          // fragment row
    const int fc = lid >> 4;          // k-half 16B chunk
    const uint32_t axor = (uint32_t)((fr & 7) << 4);

    float acc[4][4][4];
#pragma unroll
    for (int a = 0; a < 4; a++)
#pragma unroll
        for (int b = 0; b < 4; b++)
#pragma unroll
            for (int q = 0; q < 4; q++) acc[a][b][q] = 0.0f;

    load_chunk(0, 0);
    load_chunk(1, 1);

    for (int j = 0; j < NCHUNK; j++) {
        const int s = j & 1;
        if (j == NCHUNK - 1) asm volatile("cp.async.wait_group 0;" ::: "memory");
        else                 asm volatile("cp.async.wait_group 1;" ::: "memory");
        __syncthreads();

        const uint32_t As  = base + s * STAGE_BYTES;
        const uint32_t Bhs = As + TILE_BYTES;
        const uint32_t Bls = As + 2 * TILE_BYTES;

#pragma unroll
        for (int ks = 0; ks < 4; ks++) {
            const uint32_t kb = (uint32_t)(ks * 32 + fc * 16) ^ axor;

            uint32_t afr[4][4];
#pragma unroll
            for (int mi = 0; mi < 4; mi++)
                ldsm_x4(afr[mi], As + (uint32_t)((wm + mi * 16 + fr) * 128) + kb);

            uint32_t bh[2][4], bl[2][4];
#pragma unroll
            for (int nj = 0; nj < 2; nj++) {
                uint32_t rowoff = (uint32_t)((wn + nj * 16 + fr) * 128) + kb;
                ldsm_x4(bh[nj], Bhs + rowoff);
                ldsm_x4(bl[nj], Bls + rowoff);
            }
#pragma unroll
            for (int mi = 0; mi < 4; mi++)
#pragma unroll
                for (int n8 = 0; n8 < 4; n8++)
                    mma16816(acc[mi][n8], afr[mi],
                             bh[n8 >> 1][n8 & 1], bh[n8 >> 1][(n8 & 1) + 2]);
#pragma unroll
            for (int mi = 0; mi < 4; mi++)
#pragma unroll
                for (int n8 = 0; n8 < 4; n8++)
                    mma16816(acc[mi][n8], afr[mi],
                             bl[n8 >> 1][n8 & 1], bl[n8 >> 1][(n8 & 1) + 2]);
        }
        __syncthreads();
        if (j + NSTAGE < NCHUNK) load_chunk(j + NSTAGE, s);
    }

    // epilogue
    const int crow = lid >> 2;
    const int ccol = (lid & 3) * 2;
#pragma unroll
    for (int mi = 0; mi < 4; mi++) {
#pragma unroll
        for (int n8 = 0; n8 < 4; n8++) {
            float* p0 = U + (size_t)(m0 + wm + mi * 16 + crow) * N3
                          + n0 + wn + n8 * 8 + ccol;
            float* p1 = p0 + (size_t)8 * N3;
            p0[0] = acc[mi][n8][0]; p0[1] = acc[mi][n8][1];
            p1[0] = acc[mi][n8][2]; p1[1] = acc[mi][n8][3];
        }
    }
}

// ---------------------------------------------------------------------------
// SRU scan: one thread per (b,h). GS=16 prefetch groups so next-group DRAM
// latency (~600 cyc) is fully covered by current-group compute.
// ---------------------------------------------------------------------------
#define GS 16

__device__ __forceinline__ float sigmoid_fast(float x) {
    return __fdividef(1.0f, 1.0f + __expf(-x));
}

__global__ void __launch_bounds__(128) sru_scan(
    const float* __restrict__ U, const float* __restrict__ X,
    const float* __restrict__ bias,
    float* __restrict__ Hout, float* __restrict__ Cout)
{
    const int tid = blockIdx.x * blockDim.x + threadIdx.x;
    const int b = tid >> 10;
    const int h = tid & 1023;

    const float b0 = bias[h];
    const float b1 = bias[HID + h];

    const float* up = U + (size_t)b * N3 + 3 * h;
    const float* xp = X + (size_t)b * HID + h;
    float* hp = Hout + (size_t)b * HID + h;
    float* cp = Cout + (size_t)b * HID + h;

    const int USTEP = BATCH * N3;
    const int XSTEP = BATCH * HID;

    float c = 0.0f;

    float cu0[GS], cu1[GS], cu2[GS], cx[GS];
#pragma unroll
    for (int i = 0; i < GS; i++) {
        const float* u = up + (size_t)i * USTEP;
        cu0[i] = __ldcs(u + 0) + b0;
        cu1[i] = __ldcs(u + 1) + b1;
        cu2[i] = __ldcs(u + 2);
        cx[i]  = __ldcs(xp + (size_t)i * XSTEP);
    }

    const int NGROUPS = SEQ_LEN / GS;
    for (int tg = 0; tg < NGROUPS; tg++) {
        float nu0[GS], nu1[GS], nu2[GS], nx[GS];
        if (tg + 1 < NGROUPS) {
            const float* un = up + (size_t)(tg + 1) * GS * USTEP;
            const float* xn = xp + (size_t)(tg + 1) * GS * XSTEP;
#pragma unroll
            for (int i = 0; i < GS; i++) {
                const float* u = un + (size_t)i * USTEP;
                nu0[i] = __ldcs(u + 0) + b0;
                nu1[i] = __ldcs(u + 1) + b1;
                nu2[i] = __ldcs(u + 2);
                nx[i]  = __ldcs(xn + (size_t)i * XSTEP);
            }
        }

#pragma unroll
        for (int i = 0; i < GS; i++) {
            const int t = tg * GS + i;
            float f = sigmoid_fast(fmaf(b0, c, cu0[i]));
            float r = sigmoid_fast(fmaf(b1, c, cu1[i]));
            float u2 = cu2[i];
            c = fmaf(f, c - u2, u2);
            float xv = cx[i];
            float hv = fmaf(r, c - xv, xv);
            __stcs(hp + (size_t)t * XSTEP, hv);
            __stcs(cp + (size_t)t * XSTEP, c);
        }

#pragma unroll
        for (int i = 0; i < GS; i++) {
            cu0[i] = nu0[i]; cu1[i] = nu1[i]; cu2[i] = nu2[i]; cx[i] = nx[i];
        }
    }
}

// ---------------------------------------------------------------------------
// Launch
// ---------------------------------------------------------------------------
extern "C" void kernel_launch(void* const* d_in, const int* in_sizes, int n_in,
                              void* d_out, int out_size)
{
    const float* input  = (const float*)d_in[0]; // [2048,16,1024]
    const float* weight = (const float*)d_in[1]; // [1024,3072]
    const float* bias   = (const float*)d_in[2]; // [2048]
    // d_in[3] = v, intentionally unused (source quirk)

    float* Hout = (float*)d_out;
    float* Cout = (float*)d_out + SBH;

    float *U; __half *A, *Bh, *Bl;
    cudaGetSymbolAddress((void**)&U,  g_U);
    cudaGetSymbolAddress((void**)&A,  g_A);
    cudaGetSymbolAddress((void**)&Bh, g_Bh);
    cudaGetSymbolAddress((void**)&Bl, g_Bl);

    cudaFuncSetAttribute(gemm_fp16x2,
                         cudaFuncAttributeMaxDynamicSharedMemorySize, GEMM_SMEM);

    convA<<<SBH / 4 / 256, 256>>>((const float4*)input, (__half2*)A);
    convW<<<dim3(N3 / 32, KDIM / 32), dim3(32, 32)>>>(weight, Bh, Bl);

    gemm_fp16x2<<<dim3(N3 / 128, MROWS / 128), 256, GEMM_SMEM>>>(A, Bh, Bl, U);

    sru_scan<<<BATCH * HID / 128, 128>>>(U, input, bias, Hout, Cout);
}

// round 5
// speedup vs baseline: 5.3594x; 1.4666x over previous
#include <cuda_runtime.h>
#include <cuda_fp16.h>
#include <cstdint>

// ---------------------------------------------------------------------------
// Problem constants
// ---------------------------------------------------------------------------
#define SEQ_LEN   2048
#define BATCH     16
#define HID       1024
#define N3        3072
#define KDIM      1024
#define MROWS     32768
#define SBH       (SEQ_LEN * BATCH * HID)  // 33554432

// Scratch (device globals; no runtime allocation allowed)
__device__ float  g_U [(size_t)MROWS * N3];    // GEMM output [M, 3H]
__device__ __half g_A [(size_t)MROWS * KDIM];  // input fp16  [M,K]
__device__ __half g_B [(size_t)N3 * KDIM];     // weight^T fp16 [N,K]

// ---------------------------------------------------------------------------
// PTX helpers (base sm_103: cp.async + ldmatrix + mma.sync)
// ---------------------------------------------------------------------------
__device__ __forceinline__ uint32_t smem_u32(const void* p) {
    uint32_t a;
    asm("{ .reg .u64 t; cvta.to.shared.u64 t, %1; cvt.u32.u64 %0, t; }"
        : "=r"(a) : "l"(p));
    return a;
}

__device__ __forceinline__ void cpasync16(uint32_t dst, const void* src) {
    asm volatile("cp.async.cg.shared.global [%0], [%1], 16;"
        :: "r"(dst), "l"(src) : "memory");
}

__device__ __forceinline__ void ldsm_x4(uint32_t r[4], uint32_t addr) {
    asm volatile("ldmatrix.sync.aligned.m8n8.x4.shared.b16 {%0,%1,%2,%3}, [%4];"
        : "=r"(r[0]), "=r"(r[1]), "=r"(r[2]), "=r"(r[3]) : "r"(addr));
}

__device__ __forceinline__ void mma16816(float* c, const uint32_t* a,
                                         uint32_t b0, uint32_t b1) {
    asm volatile(
        "mma.sync.aligned.m16n8k16.row.col.f32.f16.f16.f32 "
        "{%0,%1,%2,%3}, {%4,%5,%6,%7}, {%8,%9}, {%0,%1,%2,%3};"
        : "+f"(c[0]), "+f"(c[1]), "+f"(c[2]), "+f"(c[3])
        : "r"(a[0]), "r"(a[1]), "r"(a[2]), "r"(a[3]), "r"(b0), "r"(b1));
}

// ---------------------------------------------------------------------------
// Conversion kernels
// ---------------------------------------------------------------------------
__global__ void __launch_bounds__(256) convA(
    const float4* __restrict__ X, __half2* __restrict__ A2)
{
    size_t i = (size_t)blockIdx.x * blockDim.x + threadIdx.x;
    float4 v = X[i];
    A2[2 * i]     = __floats2half2_rn(v.x, v.y);
    A2[2 * i + 1] = __floats2half2_rn(v.z, v.w);
}

// Transpose weight [K,N3] -> [N3,K], fp16
__global__ void __launch_bounds__(1024) convW(
    const float* __restrict__ W, __half* __restrict__ B)
{
    __shared__ float t[32][33];
    int n0 = blockIdx.x * 32, k0 = blockIdx.y * 32;
    int tx = threadIdx.x, ty = threadIdx.y;
    t[ty][tx] = W[(size_t)(k0 + ty) * N3 + n0 + tx];
    __syncthreads();
    B[(size_t)(n0 + ty) * KDIM + k0 + tx] = __float2half_rn(t[tx][ty]);
}

// ---------------------------------------------------------------------------
// fp16 GEMM via mma.sync: U = A*B^T (fp32 acc)
// CTA tile 128x128, warp tile 64x32 (2x4 warp grid), K-chunk 64.
// SMEM rows: 128B = 64 fp16 k-values, SW128 swizzle. 3-stage cp.async pipeline.
// ---------------------------------------------------------------------------
#define TKC 64
#define NCHUNK (KDIM / TKC)          // 16
#define TILE_BYTES 16384             // 128 rows x 128B
#define STAGE_BYTES (2 * TILE_BYTES) // A + B = 32KB
#define NSTAGE 3
#define GEMM_SMEM (1024 + NSTAGE * STAGE_BYTES)

__global__ void __launch_bounds__(256, 2) gemm_fp16(
    const __half* __restrict__ A, const __half* __restrict__ B,
    float* __restrict__ U)
{
    extern __shared__ char dsm[];
    const uint32_t base = (smem_u32(dsm) + 1023) & ~1023u;

    const int tid = threadIdx.x;
    const int wid = tid >> 5, lid = tid & 31;
    const int m0 = blockIdx.y * 128;
    const int n0 = blockIdx.x * 128;
    const int wm = (wid >> 2) * 64;   // warp M offset (0 or 64)
    const int wn = (wid & 3) * 32;    // warp N offset (0,32,64,96)

    // loader: 8 cp.async x 16B per thread per chunk (A tile + B tile)
    auto load_chunk = [&](int j, int s) {
        const uint32_t sb = base + s * STAGE_BYTES;
        const int koff = j * TKC;
#pragma unroll
        for (int i = 0; i < 4; i++) {
            int q = i * 256 + tid;
            int r = q >> 3, c = q & 7;
            uint32_t sw = (uint32_t)(r * 128 + ((c * 16) ^ ((r & 7) << 4)));
            cpasync16(sb + sw,              A + (size_t)(m0 + r) * KDIM + koff + c * 8);
            cpasync16(sb + TILE_BYTES + sw, B + (size_t)(n0 + r) * KDIM + koff + c * 8);
        }
        asm volatile("cp.async.commit_group;" ::: "memory");
    };

    const int fr = lid & 15;          // fragment row
    const int fc = lid >> 4;          // k-half 16B chunk
    const uint32_t axor = (uint32_t)((fr & 7) << 4);

    float acc[4][4][4];
#pragma unroll
    for (int a = 0; a < 4; a++)
#pragma unroll
        for (int b = 0; b < 4; b++)
#pragma unroll
            for (int q = 0; q < 4; q++) acc[a][b][q] = 0.0f;

    load_chunk(0, 0);
    load_chunk(1, 1);
    load_chunk(2, 2);

    for (int j = 0; j < NCHUNK; j++) {
        const int s = j % NSTAGE;
        // correct tail drain: #pending-groups we may leave incomplete shrinks
        if (j + 2 < NCHUNK)      asm volatile("cp.async.wait_group 2;" ::: "memory");
        else if (j + 1 < NCHUNK) asm volatile("cp.async.wait_group 1;" ::: "memory");
        else                     asm volatile("cp.async.wait_group 0;" ::: "memory");
        __syncthreads();

        const uint32_t As = base + s * STAGE_BYTES;
        const uint32_t Bs = As + TILE_BYTES;

#pragma unroll
        for (int ks = 0; ks < 4; ks++) {
            const uint32_t kb = (uint32_t)(ks * 32 + fc * 16) ^ axor;

            uint32_t afr[4][4];
#pragma unroll
            for (int mi = 0; mi < 4; mi++)
                ldsm_x4(afr[mi], As + (uint32_t)((wm + mi * 16 + fr) * 128) + kb);

            uint32_t bfr[2][4];
#pragma unroll
            for (int nj = 0; nj < 2; nj++)
                ldsm_x4(bfr[nj], Bs + (uint32_t)((wn + nj * 16 + fr) * 128) + kb);

#pragma unroll
            for (int mi = 0; mi < 4; mi++)
#pragma unroll
                for (int n8 = 0; n8 < 4; n8++)
                    mma16816(acc[mi][n8], afr[mi],
                             bfr[n8 >> 1][n8 & 1], bfr[n8 >> 1][(n8 & 1) + 2]);
        }
        __syncthreads();
        if (j + NSTAGE < NCHUNK) load_chunk(j + NSTAGE, s);
    }

    // epilogue
    const int crow = lid >> 2;
    const int ccol = (lid & 3) * 2;
#pragma unroll
    for (int mi = 0; mi < 4; mi++) {
#pragma unroll
        for (int n8 = 0; n8 < 4; n8++) {
            float* p0 = U + (size_t)(m0 + wm + mi * 16 + crow) * N3
                          + n0 + wn + n8 * 8 + ccol;
            float* p1 = p0 + (size_t)8 * N3;
            p0[0] = acc[mi][n8][0]; p0[1] = acc[mi][n8][1];
            p1[0] = acc[mi][n8][2]; p1[1] = acc[mi][n8][3];
        }
    }
}

// ---------------------------------------------------------------------------
// SRU scan (unchanged from R4): one thread per (b,h), GS=16 prefetch
// ---------------------------------------------------------------------------
#define GS 16

__device__ __forceinline__ float sigmoid_fast(float x) {
    return __fdividef(1.0f, 1.0f + __expf(-x));
}

__global__ void __launch_bounds__(128) sru_scan(
    const float* __restrict__ U, const float* __restrict__ X,
    const float* __restrict__ bias,
    float* __restrict__ Hout, float* __restrict__ Cout)
{
    const int tid = blockIdx.x * blockDim.x + threadIdx.x;
    const int b = tid >> 10;
    const int h = tid & 1023;

    const float b0 = bias[h];
    const float b1 = bias[HID + h];

    const float* up = U + (size_t)b * N3 + 3 * h;
    const float* xp = X + (size_t)b * HID + h;
    float* hp = Hout + (size_t)b * HID + h;
    float* cp = Cout + (size_t)b * HID + h;

    const int USTEP = BATCH * N3;
    const int XSTEP = BATCH * HID;

    float c = 0.0f;

    float cu0[GS], cu1[GS], cu2[GS], cx[GS];
#pragma unroll
    for (int i = 0; i < GS; i++) {
        const float* u = up + (size_t)i * USTEP;
        cu0[i] = __ldcs(u + 0) + b0;
        cu1[i] = __ldcs(u + 1) + b1;
        cu2[i] = __ldcs(u + 2);
        cx[i]  = __ldcs(xp + (size_t)i * XSTEP);
    }

    const int NGROUPS = SEQ_LEN / GS;
    for (int tg = 0; tg < NGROUPS; tg++) {
        float nu0[GS], nu1[GS], nu2[GS], nx[GS];
        if (tg + 1 < NGROUPS) {
            const float* un = up + (size_t)(tg + 1) * GS * USTEP;
            const float* xn = xp + (size_t)(tg + 1) * GS * XSTEP;
#pragma unroll
            for (int i = 0; i < GS; i++) {
                const float* u = un + (size_t)i * USTEP;
                nu0[i] = __ldcs(u + 0) + b0;
                nu1[i] = __ldcs(u + 1) + b1;
                nu2[i] = __ldcs(u + 2);
                nx[i]  = __ldcs(xn + (size_t)i * XSTEP);
            }
        }

#pragma unroll
        for (int i = 0; i < GS; i++) {
            const int t = tg * GS + i;
            float f = sigmoid_fast(fmaf(b0, c, cu0[i]));
            float r = sigmoid_fast(fmaf(b1, c, cu1[i]));
            float u2 = cu2[i];
            c = fmaf(f, c - u2, u2);
            float xv = cx[i];
            float hv = fmaf(r, c - xv, xv);
            __stcs(hp + (size_t)t * XSTEP, hv);
            __stcs(cp + (size_t)t * XSTEP, c);
        }

#pragma unroll
        for (int i = 0; i < GS; i++) {
            cu0[i] = nu0[i]; cu1[i] = nu1[i]; cu2[i] = nu2[i]; cx[i] = nx[i];
        }
    }
}

// ---------------------------------------------------------------------------
// Launch
// ---------------------------------------------------------------------------
extern "C" void kernel_launch(void* const* d_in, const int* in_sizes, int n_in,
                              void* d_out, int out_size)
{
    const float* input  = (const float*)d_in[0]; // [2048,16,1024]
    const float* weight = (const float*)d_in[1]; // [1024,3072]
    const float* bias   = (const float*)d_in[2]; // [2048]
    // d_in[3] = v, intentionally unused (source quirk)

    float* Hout = (float*)d_out;
    float* Cout = (float*)d_out + SBH;

    float *U; __half *A, *B;
    cudaGetSymbolAddress((void**)&U, g_U);
    cudaGetSymbolAddress((void**)&A, g_A);
    cudaGetSymbolAddress((void**)&B, g_B);

    cudaFuncSetAttribute(gemm_fp16,
                         cudaFuncAttributeMaxDynamicSharedMemorySize, GEMM_SMEM);

    convA<<<SBH / 4 / 256, 256>>>((const float4*)input, (__half2*)A);
    convW<<<dim3(N3 / 32, KDIM / 32), dim3(32, 32)>>>(weight, B);

    gemm_fp16<<<dim3(N3 / 128, MROWS / 128), 256, GEMM_SMEM>>>(A, B, U);

    sru_scan<<<BATCH * HID / 128, 128>>>(U, input, bias, Hout, Cout);
}

// round 6
// speedup vs baseline: 6.2562x; 1.1673x over previous
#include <cuda_runtime.h>
#include <cuda_fp16.h>
#include <cstdint>

// ---------------------------------------------------------------------------
// Problem constants
// ---------------------------------------------------------------------------
#define SEQ_LEN   2048
#define BATCH     16
#define HID       1024
#define N3        3072
#define KDIM      1024
#define MROWS     32768
#define SBH       (SEQ_LEN * BATCH * HID)  // 33554432

// Scratch (device globals; no runtime allocation allowed)
__device__ __half g_U[(size_t)MROWS * N3];    // GEMM output [M, 3H], fp16
__device__ __half g_A[(size_t)MROWS * KDIM];  // input fp16  [M,K]
__device__ __half g_B[(size_t)N3 * KDIM];     // weight^T fp16 [N,K]

// ---------------------------------------------------------------------------
// PTX helpers (base sm_103: cp.async + ldmatrix + mma.sync)
// ---------------------------------------------------------------------------
__device__ __forceinline__ uint32_t smem_u32(const void* p) {
    uint32_t a;
    asm("{ .reg .u64 t; cvta.to.shared.u64 t, %1; cvt.u32.u64 %0, t; }"
        : "=r"(a) : "l"(p));
    return a;
}

__device__ __forceinline__ void cpasync16(uint32_t dst, const void* src) {
    asm volatile("cp.async.cg.shared.global [%0], [%1], 16;"
        :: "r"(dst), "l"(src) : "memory");
}

__device__ __forceinline__ void ldsm_x4(uint32_t r[4], uint32_t addr) {
    asm volatile("ldmatrix.sync.aligned.m8n8.x4.shared.b16 {%0,%1,%2,%3}, [%4];"
        : "=r"(r[0]), "=r"(r[1]), "=r"(r[2]), "=r"(r[3]) : "r"(addr));
}

__device__ __forceinline__ void mma16816(float* c, const uint32_t* a,
                                         uint32_t b0, uint32_t b1) {
    asm volatile(
        "mma.sync.aligned.m16n8k16.row.col.f32.f16.f16.f32 "
        "{%0,%1,%2,%3}, {%4,%5,%6,%7}, {%8,%9}, {%0,%1,%2,%3};"
        : "+f"(c[0]), "+f"(c[1]), "+f"(c[2]), "+f"(c[3])
        : "r"(a[0]), "r"(a[1]), "r"(a[2]), "r"(a[3]), "r"(b0), "r"(b1));
}

// ---------------------------------------------------------------------------
// Conversion kernels
// ---------------------------------------------------------------------------
__global__ void __launch_bounds__(256) convA(
    const float4* __restrict__ X, __half2* __restrict__ A2)
{
    size_t i = (size_t)blockIdx.x * blockDim.x + threadIdx.x;
    float4 v = X[i];
    A2[2 * i]     = __floats2half2_rn(v.x, v.y);
    A2[2 * i + 1] = __floats2half2_rn(v.z, v.w);
}

// Transpose weight [K,N3] -> [N3,K], fp16
__global__ void __launch_bounds__(1024) convW(
    const float* __restrict__ W, __half* __restrict__ B)
{
    __shared__ float t[32][33];
    int n0 = blockIdx.x * 32, k0 = blockIdx.y * 32;
    int tx = threadIdx.x, ty = threadIdx.y;
    t[ty][tx] = W[(size_t)(k0 + ty) * N3 + n0 + tx];
    __syncthreads();
    B[(size_t)(n0 + ty) * KDIM + k0 + tx] = __float2half_rn(t[tx][ty]);
}

// ---------------------------------------------------------------------------
// fp16 GEMM via mma.sync: U(fp16) = A*B^T (fp32 acc)
// CTA tile 128x128, warp tile 64x32, K-chunk 64. SW128 smem.
// 3-stage ring, single __syncthreads per chunk (cutlass-style multistage).
// ---------------------------------------------------------------------------
#define TKC 64
#define NCHUNK (KDIM / TKC)          // 16
#define TILE_BYTES 16384             // 128 rows x 128B
#define STAGE_BYTES (2 * TILE_BYTES) // A + B = 32KB
#define NSTAGE 3
#define GEMM_SMEM (1024 + NSTAGE * STAGE_BYTES)

__global__ void __launch_bounds__(256, 2) gemm_fp16(
    const __half* __restrict__ A, const __half* __restrict__ B,
    __half* __restrict__ U)
{
    extern __shared__ char dsm[];
    const uint32_t base = (smem_u32(dsm) + 1023) & ~1023u;

    const int tid = threadIdx.x;
    const int wid = tid >> 5, lid = tid & 31;
    const int m0 = blockIdx.y * 128;
    const int n0 = blockIdx.x * 128;
    const int wm = (wid >> 2) * 64;
    const int wn = (wid & 3) * 32;

    auto load_chunk = [&](int j, int s) {
        const uint32_t sb = base + s * STAGE_BYTES;
        const int koff = j * TKC;
#pragma unroll
        for (int i = 0; i < 4; i++) {
            int q = i * 256 + tid;
            int r = q >> 3, c = q & 7;
            uint32_t sw = (uint32_t)(r * 128 + ((c * 16) ^ ((r & 7) << 4)));
            cpasync16(sb + sw,              A + (size_t)(m0 + r) * KDIM + koff + c * 8);
            cpasync16(sb + TILE_BYTES + sw, B + (size_t)(n0 + r) * KDIM + koff + c * 8);
        }
        asm volatile("cp.async.commit_group;" ::: "memory");
    };

    const int fr = lid & 15;
    const int fc = lid >> 4;
    const uint32_t axor = (uint32_t)((fr & 7) << 4);

    float acc[4][4][4];
#pragma unroll
    for (int a = 0; a < 4; a++)
#pragma unroll
        for (int b = 0; b < 4; b++)
#pragma unroll
            for (int q = 0; q < 4; q++) acc[a][b][q] = 0.0f;

    load_chunk(0, 0);
    load_chunk(1, 1);

    for (int j = 0; j < NCHUNK; j++) {
        const int s = j % NSTAGE;
        if (j + 1 < NCHUNK) asm volatile("cp.async.wait_group 1;" ::: "memory");
        else                asm volatile("cp.async.wait_group 0;" ::: "memory");
        __syncthreads();
        // stage (j+2)%3 == (j-1)%3 was consumed at iter j-1; the sync above
        // makes that consumption block-wide complete before we overwrite it.
        if (j + 2 < NCHUNK) load_chunk(j + 2, (j + 2) % NSTAGE);

        const uint32_t As = base + s * STAGE_BYTES;
        const uint32_t Bs = As + TILE_BYTES;

#pragma unroll
        for (int ks = 0; ks < 4; ks++) {
            const uint32_t kb = (uint32_t)(ks * 32 + fc * 16) ^ axor;

            uint32_t afr[4][4];
#pragma unroll
            for (int mi = 0; mi < 4; mi++)
                ldsm_x4(afr[mi], As + (uint32_t)((wm + mi * 16 + fr) * 128) + kb);

            uint32_t bfr[2][4];
#pragma unroll
            for (int nj = 0; nj < 2; nj++)
                ldsm_x4(bfr[nj], Bs + (uint32_t)((wn + nj * 16 + fr) * 128) + kb);

#pragma unroll
            for (int mi = 0; mi < 4; mi++)
#pragma unroll
                for (int n8 = 0; n8 < 4; n8++)
                    mma16816(acc[mi][n8], afr[mi],
                             bfr[n8 >> 1][n8 & 1], bfr[n8 >> 1][(n8 & 1) + 2]);
        }
    }

    // epilogue: fp32 acc -> fp16 U
    const int crow = lid >> 2;
    const int ccol = (lid & 3) * 2;
#pragma unroll
    for (int mi = 0; mi < 4; mi++) {
#pragma unroll
        for (int n8 = 0; n8 < 4; n8++) {
            __half* p0 = U + (size_t)(m0 + wm + mi * 16 + crow) * N3
                           + n0 + wn + n8 * 8 + ccol;
            __half* p1 = p0 + (size_t)8 * N3;
            *(__half2*)p0 = __floats2half2_rn(acc[mi][n8][0], acc[mi][n8][1]);
            *(__half2*)p1 = __floats2half2_rn(acc[mi][n8][2], acc[mi][n8][3]);
        }
    }
}

// ---------------------------------------------------------------------------
// SRU scan with cp.async smem staging.
// Block = 128 threads = 128 h-chains (one b, one 128-h slab).
// Groups of 16 timesteps; per group: U 768B/step + X 512B/step = 20KB.
// 3-stage smem ring, deep cp.async queue -> DRAM concurrency no longer
// bounded by per-warp LDG limits.
// ---------------------------------------------------------------------------
#define SGS 16
#define GRP_U (SGS * 768)            // 12288
#define GRP_X (SGS * 512)            // 8192
#define GRP_BYTES (GRP_U + GRP_X)    // 20480
#define NGR (SEQ_LEN / SGS)          // 128
#define SCAN_SMEM (3 * GRP_BYTES)    // 61440

__device__ __forceinline__ float sigmoid_fast(float x) {
    return __fdividef(1.0f, 1.0f + __expf(-x));
}

__global__ void __launch_bounds__(128) sru_scan(
    const __half* __restrict__ Uh, const float* __restrict__ X,
    const float* __restrict__ bias,
    float* __restrict__ Hout, float* __restrict__ Cout)
{
    extern __shared__ char ssm[];
    const uint32_t sbase = smem_u32(ssm);
    const int tid = threadIdx.x;
    const int b   = blockIdx.x >> 3;
    const int hb  = blockIdx.x & 7;
    const int h   = hb * 128 + tid;

    const float b0 = bias[h];
    const float b1 = bias[HID + h];

    // loader chunk geometry (per-thread, constant across groups)
    int us[6], uc[6], xs[4], xc[4];
#pragma unroll
    for (int k = 0; k < 6; k++) { int q = tid + 128 * k; us[k] = q / 48; uc[k] = q % 48; }
#pragma unroll
    for (int k = 0; k < 4; k++) { int q = tid + 128 * k; xs[k] = q / 32; xc[k] = q % 32; }

    const size_t UT = (size_t)BATCH * N3;    // halves per timestep
    const size_t XT = (size_t)BATCH * HID;   // floats per timestep

    const __half* Ublk = Uh + (size_t)b * N3 + hb * 384;
    const float*  Xblk = X  + (size_t)b * HID + hb * 128;

    auto load_group = [&](int g, int s) {
        const uint32_t sb = sbase + s * GRP_BYTES;
        const __half* Ug = Ublk + (size_t)g * SGS * UT;
        const float*  Xg = Xblk + (size_t)g * SGS * XT;
#pragma unroll
        for (int k = 0; k < 6; k++)
            cpasync16(sb + us[k] * 768 + uc[k] * 16,
                      Ug + (size_t)us[k] * UT + uc[k] * 8);
#pragma unroll
        for (int k = 0; k < 4; k++)
            cpasync16(sb + GRP_U + xs[k] * 512 + xc[k] * 16,
                      Xg + (size_t)xs[k] * XT + xc[k] * 4);
        asm volatile("cp.async.commit_group;" ::: "memory");
    };

    load_group(0, 0);
    load_group(1, 1);

    float c = 0.0f;
    float* hp = Hout + (size_t)b * HID + h;
    float* cp = Cout + (size_t)b * HID + h;

    for (int g = 0; g < NGR; g++) {
        const int s = g % 3;
        if (g + 1 < NGR) asm volatile("cp.async.wait_group 1;" ::: "memory");
        else             asm volatile("cp.async.wait_group 0;" ::: "memory");
        __syncthreads();
        if (g + 2 < NGR) load_group(g + 2, (g + 2) % 3);

        const char* ub = ssm + s * GRP_BYTES;
        const char* xb = ub + GRP_U;
#pragma unroll
        for (int i = 0; i < SGS; i++) {
            const __half* up = (const __half*)(ub + i * 768) + 3 * tid;
            float u0 = __half2float(up[0]) + b0;
            float u1 = __half2float(up[1]) + b1;
            float u2 = __half2float(up[2]);
            float xv = *(const float*)(xb + i * 512 + 4 * tid);

            float f = sigmoid_fast(fmaf(b0, c, u0));
            float r = sigmoid_fast(fmaf(b1, c, u1));
            c = fmaf(f, c - u2, u2);
            float hv = fmaf(r, c - xv, xv);

            const size_t off = (size_t)(g * SGS + i) * XT;
            __stcs(hp + off, hv);
            __stcs(cp + off, c);
        }
    }
}

// ---------------------------------------------------------------------------
// Launch
// ---------------------------------------------------------------------------
extern "C" void kernel_launch(void* const* d_in, const int* in_sizes, int n_in,
                              void* d_out, int out_size)
{
    const float* input  = (const float*)d_in[0]; // [2048,16,1024]
    const float* weight = (const float*)d_in[1]; // [1024,3072]
    const float* bias   = (const float*)d_in[2]; // [2048]
    // d_in[3] = v, intentionally unused (source quirk)

    float* Hout = (float*)d_out;
    float* Cout = (float*)d_out + SBH;

    __half *U, *A, *B;
    cudaGetSymbolAddress((void**)&U, g_U);
    cudaGetSymbolAddress((void**)&A, g_A);
    cudaGetSymbolAddress((void**)&B, g_B);

    cudaFuncSetAttribute(gemm_fp16,
                         cudaFuncAttributeMaxDynamicSharedMemorySize, GEMM_SMEM);
    cudaFuncSetAttribute(sru_scan,
                         cudaFuncAttributeMaxDynamicSharedMemorySize, SCAN_SMEM);

    convA<<<SBH / 4 / 256, 256>>>((const float4*)input, (__half2*)A);
    convW<<<dim3(N3 / 32, KDIM / 32), dim3(32, 32)>>>(weight, B);

    gemm_fp16<<<dim3(N3 / 128, MROWS / 128), 256, GEMM_SMEM>>>(A, B, U);

    sru_scan<<<128, 128, SCAN_SMEM>>>(U, input, bias, Hout, Cout);
}